// round 8
// baseline (speedup 1.0000x reference)
#include <cuda_runtime.h>
#include <cuda_fp16.h>
#include <cstdint>

#define NTOT 16384
#define KN   16
#define NP   15
#define CIN  64
#define COUT 128
#define KTOT (NP * CIN)        // 960

// ---------------- global scratch (allowed: __device__ arrays) ----------------
__device__ __half g_A[(size_t)NTOT * KTOT];     // [n][k] k-major, fp16
__device__ __half g_B[COUT * KTOT];             // [cout][k] k-major (= W^T), fp16

typedef unsigned long long u64;
typedef unsigned int u32;

__device__ __forceinline__ u64 pack2(float lo, float hi) {
    u64 r; asm("mov.b64 %0, {%1, %2};" : "=l"(r) : "f"(lo), "f"(hi)); return r;
}
__device__ __forceinline__ void unpack2(u64 v, float &lo, float &hi) {
    asm("mov.b64 {%0, %1}, %2;" : "=f"(lo), "=f"(hi) : "l"(v));
}
__device__ __forceinline__ void fma2(u64 &d, u64 a, u64 b) {
    asm("fma.rn.f32x2 %0, %1, %2, %3;" : "=l"(d) : "l"(a), "l"(b), "l"(d));
}
__device__ __forceinline__ u32 h2pk(float a, float b) {
    __half ha = __float2half_rn(a), hb = __float2half_rn(b);
    unsigned short ua = *reinterpret_cast<unsigned short*>(&ha);
    unsigned short ub = *reinterpret_cast<unsigned short*>(&hb);
    return (u32)ua | ((u32)ub << 16);
}
__device__ __forceinline__ u32 smem_u32(const void* p) {
    u32 a; asm("{ .reg .u64 t; cvta.to.shared.u64 t, %1; cvt.u32.u64 %0, t; }"
               : "=r"(a) : "l"(p));
    return a;
}
__device__ __forceinline__ void ldmx4(u32* r, u32 addr) {
    asm volatile("ldmatrix.sync.aligned.m8n8.x4.shared.b16 {%0,%1,%2,%3}, [%4];"
                 : "=r"(r[0]), "=r"(r[1]), "=r"(r[2]), "=r"(r[3]) : "r"(addr));
}
__device__ __forceinline__ void mma_f16(float* d, const u32* a, const u32* b) {
    asm volatile("mma.sync.aligned.m16n8k16.row.col.f32.f16.f16.f32 "
                 "{%0,%1,%2,%3}, {%4,%5,%6,%7}, {%8,%9}, {%0,%1,%2,%3};"
                 : "+f"(d[0]), "+f"(d[1]), "+f"(d[2]), "+f"(d[3])
                 : "r"(a[0]), "r"(a[1]), "r"(a[2]), "r"(a[3]),
                   "r"(b[0]), "r"(b[1]));
}

// ====== kernel 1: gather + influence + aggregation (+ fused W conversion) ======
// warp-per-query: 8 queries/CTA, 256 threads; lane owns 2 channels.
// Influences stored PRE-DUPLICATED as u64 (f32x2) to feed fma2 directly.
#define Q1 8
#define NT1 256
__global__ __launch_bounds__(NT1)
void k1_agg(const float* __restrict__ query,
            const float* __restrict__ support,
            const int*   __restrict__ nidx,
            const float* __restrict__ feats,
            const float* __restrict__ kp,
            const float* __restrict__ W)
{
    __shared__ u64   s_infl2[Q1 * KN * 16];   // [pair][p] duplicated f32x2, 16KB
    __shared__ float s_kp[48];
    __shared__ float s_q[Q1 * 3];
    __shared__ int   s_nidx[Q1 * KN];

    const int tid = threadIdx.x;
    const int n0  = blockIdx.x * Q1;

    if (tid < Q1 * KN)  s_nidx[tid] = nidx[n0 * KN + tid];
    if (tid < NP * 3)   s_kp[tid]   = kp[tid];
    if (tid < Q1 * 3)   s_q[tid]    = query[n0 * 3 + tid];
    __syncthreads();

    // influences: one (q,k) pair per thread (128 pairs), duplicated u64 store
    if (tid < Q1 * KN) {
        int pair = tid;
        int qq = pair >> 4;
        int m  = s_nidx[pair];
        float rx = support[m * 3 + 0] - s_q[qq * 3 + 0];
        float ry = support[m * 3 + 1] - s_q[qq * 3 + 1];
        float rz = support[m * 3 + 2] - s_q[qq * 3 + 2];
        u64* ob = s_infl2 + pair * 16;
        #pragma unroll
        for (int p = 0; p < NP; p++) {
            float dx = rx - s_kp[p * 3 + 0];
            float dy = ry - s_kp[p * 3 + 1];
            float dz = rz - s_kp[p * 3 + 2];
            float d  = sqrtf(fmaf(dx, dx, fmaf(dy, dy, dz * dz)));
            float v  = fmaxf(1.0f - d, 0.0f);
            ob[p] = pack2(v, v);
        }
        ob[15] = 0ULL;
    }
    __syncthreads();

    const int q    = tid >> 5;          // warp id = query
    const int lane = tid & 31;
    const int ch   = lane << 1;         // 2 channels per lane

    u64 acc[NP];
    #pragma unroll
    for (int p = 0; p < NP; p++) acc[p] = 0ULL;

    #pragma unroll
    for (int k = 0; k < KN; k++) {
        int m = s_nidx[q * KN + k];
        float2 f = __ldg((const float2*)(feats + (size_t)m * CIN + ch));
        u64 fx = pack2(f.x, f.y);
        const ulonglong2* ib = (const ulonglong2*)(s_infl2 + (q * KN + k) * 16);
        ulonglong2 v0 = ib[0], v1 = ib[1], v2 = ib[2], v3 = ib[3];
        ulonglong2 v4 = ib[4], v5 = ib[5], v6 = ib[6], v7 = ib[7];
        fma2(acc[0],  v0.x, fx); fma2(acc[1],  v0.y, fx);
        fma2(acc[2],  v1.x, fx); fma2(acc[3],  v1.y, fx);
        fma2(acc[4],  v2.x, fx); fma2(acc[5],  v2.y, fx);
        fma2(acc[6],  v3.x, fx); fma2(acc[7],  v3.y, fx);
        fma2(acc[8],  v4.x, fx); fma2(acc[9],  v4.y, fx);
        fma2(acc[10], v5.x, fx); fma2(acc[11], v5.y, fx);
        fma2(acc[12], v6.x, fx); fma2(acc[13], v6.y, fx);
        fma2(acc[14], v7.x, fx);
    }

    // store A as fp16 (2 channels -> one u32 per p; warp = 128B contiguous)
    const size_t rowbase = (size_t)(n0 + q) * KTOT + ch;
    #pragma unroll
    for (int p = 0; p < NP; p++) {
        float a0, a1;
        unpack2(acc[p], a0, a1);
        *(u32*)(g_A + rowbase + p * CIN) = h2pk(a0, a1);
    }

    // ---- fused W conversion: blocks 0..119 convert W -> B fp16 ----
    if (blockIdx.x < 120) {
        int idx4 = blockIdx.x * NT1 + tid;     // 0..30719, 4 k-elems each
        int n  = idx4 / 240;
        int kq = idx4 - n * 240;
        int k  = kq * 4;
        int p  = k >> 6, cin = k & 63;
        const float* wp = W + p * CIN * COUT + cin * COUT + n;
        float w0 = __ldg(wp);
        float w1 = __ldg(wp + COUT);
        float w2 = __ldg(wp + 2 * COUT);
        float w3 = __ldg(wp + 3 * COUT);
        uint2 vh = make_uint2(h2pk(w0, w1), h2pk(w2, w3));
        *(uint2*)(g_B + (size_t)n * KTOT + k) = vh;
    }
}

// ================= kernel 2: mma.sync fp16 GEMM (single product) =================
// D[16384 x 128] = A * B^T ; M-tile 128, N=128, K=960.
// 256 threads, 8 warps in 2(M) x 4(N); each warp 64x32.
// smem: 2 buffers x 2 tiles x [128 rows x 128B] = 65536 bytes.
#define NT2 256
#define NCHUNK 15
#define TILEB 16384
#define BUFB  (2 * TILEB)

__global__ __launch_bounds__(NT2, 1)
void k2_gemm(float* __restrict__ out)
{
    extern __shared__ char smem[];
    const u32 sb = smem_u32(smem);
    const int tid  = threadIdx.x;
    const int wid  = tid >> 5;
    const int lane = tid & 31;
    const int wm   = wid >> 2;       // 0..1  (M groups of 64)
    const int wn   = wid & 3;        // 0..3  (N groups of 32)
    const int m0   = blockIdx.x * 128;

    // ldmatrix per-thread addressing (swizzle: row*128 + (o ^ (row&7)*16))
    const int a_row  = wm * 64 + (lane & 7) + ((lane >> 3) & 1) * 8;  // + mi*16
    const int a_bh   = ((lane >> 4) & 1) * 16;
    const u32 a_mask = (u32)((a_row & 7) * 16);
    const int b_row  = wn * 32 + (lane & 7) + ((lane >> 4) & 1) * 8;  // + nj*16
    const int b_bh   = ((lane >> 3) & 1) * 16;
    const u32 b_mask = (u32)((b_row & 7) * 16);

    float acc[4][4][4];
    #pragma unroll
    for (int mi = 0; mi < 4; mi++)
        #pragma unroll
        for (int ni = 0; ni < 4; ni++)
            #pragma unroll
            for (int e = 0; e < 4; e++) acc[mi][ni][e] = 0.0f;

    // ---- async load of one chunk into buffer (c&1): 2 tiles ----
    auto load_chunk = [&](int c) {
        u32 dstb = sb + (u32)(c & 1) * BUFB;
        #pragma unroll
        for (int j = 0; j < 8; j++) {
            int idx = tid + j * NT2;              // 0..2047
            int t    = idx >> 10;                 // 0:A 1:B
            int win  = idx & 1023;
            int row  = win >> 3;
            int c16  = win & 7;
            const __half* src = (t == 0 ? g_A + (size_t)(m0 + row) * KTOT
                                        : g_B + (size_t)row * KTOT)
                                + c * 64 + c16 * 8;
            u32 dst = dstb + (u32)t * TILEB
                    + (u32)(row * 128 + ((c16 * 16) ^ ((row & 7) * 16)));
            asm volatile("cp.async.cg.shared.global [%0], [%1], 16;"
                         :: "r"(dst), "l"(src) : "memory");
        }
        asm volatile("cp.async.commit_group;" ::: "memory");
    };

    load_chunk(0);

    for (int c = 0; c < NCHUNK; c++) {
        if (c + 1 < NCHUNK) {
            load_chunk(c + 1);
            asm volatile("cp.async.wait_group 1;" ::: "memory");
        } else {
            asm volatile("cp.async.wait_group 0;" ::: "memory");
        }
        __syncthreads();

        const u32 bufb  = sb + (u32)(c & 1) * BUFB;
        const u32 aBase = bufb + (u32)(a_row * 128);
        const u32 bBase = bufb + TILEB + (u32)(b_row * 128);

        #pragma unroll
        for (int ks = 0; ks < 4; ks++) {
            const u32 aOff = (u32)((ks * 32 + a_bh)) ^ a_mask;
            const u32 bOff = (u32)((ks * 32 + b_bh)) ^ b_mask;

            u32 b[8];
            #pragma unroll
            for (int nj = 0; nj < 2; nj++)
                ldmx4(&b[nj * 4], bBase + (u32)(nj * 16 * 128) + bOff);

            #pragma unroll
            for (int mi = 0; mi < 4; mi++) {
                u32 a[4];
                ldmx4(a, aBase + (u32)(mi * 16 * 128) + aOff);
                #pragma unroll
                for (int ni = 0; ni < 4; ni++)
                    mma_f16(acc[mi][ni], a, &b[(ni >> 1) * 4 + (ni & 1) * 2]);
            }
        }
        __syncthreads();
    }

    // ---- epilogue ----
    #pragma unroll
    for (int mi = 0; mi < 4; mi++) {
        int row = m0 + wm * 64 + mi * 16 + (lane >> 2);
        #pragma unroll
        for (int ni = 0; ni < 4; ni++) {
            int col = wn * 32 + ni * 8 + (lane & 3) * 2;
            *(float2*)(out + (size_t)row * COUT + col) =
                make_float2(acc[mi][ni][0], acc[mi][ni][1]);
            *(float2*)(out + (size_t)(row + 8) * COUT + col) =
                make_float2(acc[mi][ni][2], acc[mi][ni][3]);
        }
    }
}

// ================= launch =================
extern "C" void kernel_launch(void* const* d_in, const int* in_sizes, int n_in,
                              void* d_out, int out_size) {
    const float* query   = (const float*)d_in[0];
    const float* support = (const float*)d_in[1];
    const int*   nidx    = (const int*)d_in[2];
    const float* feats   = (const float*)d_in[3];
    const float* W       = (const float*)d_in[4];
    const float* kp      = (const float*)d_in[5];
    float* out = (float*)d_out;

    k1_agg<<<NTOT / Q1, NT1>>>(query, support, nidx, feats, kp, W);

    const int smem2 = 2 * BUFB;   // 65536
    cudaFuncSetAttribute(k2_gemm, cudaFuncAttributeMaxDynamicSharedMemorySize, smem2);
    k2_gemm<<<NTOT / 128, NT2, smem2>>>(out);
}

// round 9
// speedup vs baseline: 1.1592x; 1.1592x over previous
#include <cuda_runtime.h>
#include <cuda_fp16.h>
#include <cstdint>

#define NTOT 16384
#define KN   16
#define NP   15
#define CIN  64
#define COUT 128
#define KTOT (NP * CIN)        // 960

// ---------------- global scratch (allowed: __device__ arrays) ----------------
__device__ __half g_A[(size_t)NTOT * KTOT];     // [n][k] k-major, fp16
__device__ __half g_B[COUT * KTOT];             // [cout][k] k-major (= W^T), fp16

typedef unsigned long long u64;
typedef unsigned int u32;

__device__ __forceinline__ u64 pack2(float lo, float hi) {
    u64 r; asm("mov.b64 %0, {%1, %2};" : "=l"(r) : "f"(lo), "f"(hi)); return r;
}
__device__ __forceinline__ void unpack2(u64 v, float &lo, float &hi) {
    asm("mov.b64 {%0, %1}, %2;" : "=f"(lo), "=f"(hi) : "l"(v));
}
__device__ __forceinline__ void fma2(u64 &d, u64 a, u64 b) {
    asm("fma.rn.f32x2 %0, %1, %2, %3;" : "=l"(d) : "l"(a), "l"(b), "l"(d));
}
__device__ __forceinline__ u32 h2pk(float a, float b) {
    __half ha = __float2half_rn(a), hb = __float2half_rn(b);
    unsigned short ua = *reinterpret_cast<unsigned short*>(&ha);
    unsigned short ub = *reinterpret_cast<unsigned short*>(&hb);
    return (u32)ua | ((u32)ub << 16);
}
__device__ __forceinline__ u32 smem_u32(const void* p) {
    u32 a; asm("{ .reg .u64 t; cvta.to.shared.u64 t, %1; cvt.u32.u64 %0, t; }"
               : "=r"(a) : "l"(p));
    return a;
}
__device__ __forceinline__ void ldmx4(u32* r, u32 addr) {
    asm volatile("ldmatrix.sync.aligned.m8n8.x4.shared.b16 {%0,%1,%2,%3}, [%4];"
                 : "=r"(r[0]), "=r"(r[1]), "=r"(r[2]), "=r"(r[3]) : "r"(addr));
}
__device__ __forceinline__ void mma_f16(float* d, const u32* a, const u32* b) {
    asm volatile("mma.sync.aligned.m16n8k16.row.col.f32.f16.f16.f32 "
                 "{%0,%1,%2,%3}, {%4,%5,%6,%7}, {%8,%9}, {%0,%1,%2,%3};"
                 : "+f"(d[0]), "+f"(d[1]), "+f"(d[2]), "+f"(d[3])
                 : "r"(a[0]), "r"(a[1]), "r"(a[2]), "r"(a[3]),
                   "r"(b[0]), "r"(b[1]));
}

// ====== kernel 1: gather + influence + aggregation (+ fused W conversion) ======
// warp-per-query: 8 queries/CTA, 256 threads; lane owns 2 channels.
// Influences duplicated f32x2 in TRANSPOSED layout [p][pair]:
//   - stores: lane-consecutive STS.64, conflict-free
//   - agg reads: warp-uniform LDS.64 broadcast, conflict-free
#define Q1 8
#define NT1 256
#define IPITCH 136   // u64 per p-row (128 pairs + pad)

__global__ __launch_bounds__(NT1)
void k1_agg(const float* __restrict__ query,
            const float* __restrict__ support,
            const int*   __restrict__ nidx,
            const float* __restrict__ feats,
            const float* __restrict__ kp,
            const float* __restrict__ W)
{
    __shared__ u64   s_infl2[NP * IPITCH];    // [p][pair]
    __shared__ float s_kp[48];
    __shared__ float s_q[Q1 * 3];
    __shared__ int   s_nidx[Q1 * KN];

    const int tid = threadIdx.x;
    const int n0  = blockIdx.x * Q1;

    if (tid < Q1 * KN)  s_nidx[tid] = nidx[n0 * KN + tid];
    if (tid < NP * 3)   s_kp[tid]   = kp[tid];
    if (tid < Q1 * 3)   s_q[tid]    = query[n0 * 3 + tid];
    __syncthreads();

    // influences: 2 threads per (q,k) pair, each handles ~half the p's
    {
        int pair = tid >> 1;           // 0..127
        int half = tid & 1;            // 0: p 0..7, 1: p 8..14
        int qq = pair >> 4;
        int m  = s_nidx[pair];
        float rx = support[m * 3 + 0] - s_q[qq * 3 + 0];
        float ry = support[m * 3 + 1] - s_q[qq * 3 + 1];
        float rz = support[m * 3 + 2] - s_q[qq * 3 + 2];
        int p0 = half * 8;
        int p1 = half ? NP : 8;
        #pragma unroll
        for (int p = p0; p < p1; p++) {
            float dx = rx - s_kp[p * 3 + 0];
            float dy = ry - s_kp[p * 3 + 1];
            float dz = rz - s_kp[p * 3 + 2];
            float d  = sqrtf(fmaf(dx, dx, fmaf(dy, dy, dz * dz)));
            float v  = fmaxf(1.0f - d, 0.0f);
            s_infl2[p * IPITCH + pair] = pack2(v, v);
        }
    }
    __syncthreads();

    const int q    = tid >> 5;          // warp id = query
    const int lane = tid & 31;
    const int ch   = lane << 1;         // 2 channels per lane

    u64 acc[NP];
    #pragma unroll
    for (int p = 0; p < NP; p++) acc[p] = 0ULL;

    #pragma unroll
    for (int k = 0; k < KN; k++) {
        int m = s_nidx[q * KN + k];
        float2 f = __ldg((const float2*)(feats + (size_t)m * CIN + ch));
        u64 fx = pack2(f.x, f.y);
        const int pair = q * KN + k;
        #pragma unroll
        for (int p = 0; p < NP; p++)
            fma2(acc[p], s_infl2[p * IPITCH + pair], fx);
    }

    // store A as fp16 (2 channels -> one u32 per p; warp = 128B contiguous)
    const size_t rowbase = (size_t)(n0 + q) * KTOT + ch;
    #pragma unroll
    for (int p = 0; p < NP; p++) {
        float a0, a1;
        unpack2(acc[p], a0, a1);
        *(u32*)(g_A + rowbase + p * CIN) = h2pk(a0, a1);
    }

    // ---- fused W conversion: blocks 0..119 convert W -> B fp16 ----
    if (blockIdx.x < 120) {
        int idx4 = blockIdx.x * NT1 + tid;     // 0..30719, 4 k-elems each
        int n  = idx4 / 240;
        int kq = idx4 - n * 240;
        int k  = kq * 4;
        int p  = k >> 6, cin = k & 63;
        const float* wp = W + p * CIN * COUT + cin * COUT + n;
        float w0 = __ldg(wp);
        float w1 = __ldg(wp + COUT);
        float w2 = __ldg(wp + 2 * COUT);
        float w3 = __ldg(wp + 3 * COUT);
        uint2 vh = make_uint2(h2pk(w0, w1), h2pk(w2, w3));
        *(uint2*)(g_B + (size_t)n * KTOT + k) = vh;
    }
}

// ================= kernel 2: mma.sync fp16 GEMM (single product) =================
// D[16384 x 128] = A * B^T ; M-tile 128, N=128, K=960.
// 256 threads, 8 warps in 2(M) x 4(N); each warp 64x32.
// smem: 3 stages x 2 tiles x 16KB = 98304 bytes.
#define NT2 256
#define NCHUNK 15
#define TILEB 16384
#define BUFB  (2 * TILEB)

__global__ __launch_bounds__(NT2, 1)
void k2_gemm(float* __restrict__ out)
{
    extern __shared__ char smem[];
    const u32 sb = smem_u32(smem);
    const int tid  = threadIdx.x;
    const int wid  = tid >> 5;
    const int lane = tid & 31;
    const int wm   = wid >> 2;       // 0..1  (M groups of 64)
    const int wn   = wid & 3;        // 0..3  (N groups of 32)
    const int m0   = blockIdx.x * 128;

    // ldmatrix per-thread addressing (swizzle: row*128 + (o ^ (row&7)*16))
    const int a_row  = wm * 64 + (lane & 7) + ((lane >> 3) & 1) * 8;  // + mi*16
    const int a_bh   = ((lane >> 4) & 1) * 16;
    const u32 a_mask = (u32)((a_row & 7) * 16);
    const int b_row  = wn * 32 + (lane & 7) + ((lane >> 4) & 1) * 8;  // + nj*16
    const int b_bh   = ((lane >> 3) & 1) * 16;
    const u32 b_mask = (u32)((b_row & 7) * 16);

    float acc[4][4][4];
    #pragma unroll
    for (int mi = 0; mi < 4; mi++)
        #pragma unroll
        for (int ni = 0; ni < 4; ni++)
            #pragma unroll
            for (int e = 0; e < 4; e++) acc[mi][ni][e] = 0.0f;

    // ---- async load of one chunk into stage (c % 3): 2 tiles ----
    auto load_chunk = [&](int c) {
        u32 dstb = sb + (u32)(c % 3) * BUFB;
        #pragma unroll
        for (int j = 0; j < 8; j++) {
            int idx = tid + j * NT2;              // 0..2047
            int t    = idx >> 10;                 // 0:A 1:B
            int win  = idx & 1023;
            int row  = win >> 3;
            int c16  = win & 7;
            const __half* src = (t == 0 ? g_A + (size_t)(m0 + row) * KTOT
                                        : g_B + (size_t)row * KTOT)
                                + c * 64 + c16 * 8;
            u32 dst = dstb + (u32)t * TILEB
                    + (u32)(row * 128 + ((c16 * 16) ^ ((row & 7) * 16)));
            asm volatile("cp.async.cg.shared.global [%0], [%1], 16;"
                         :: "r"(dst), "l"(src) : "memory");
        }
        asm volatile("cp.async.commit_group;" ::: "memory");
    };

    load_chunk(0);
    load_chunk(1);

    for (int c = 0; c < NCHUNK; c++) {
        if (c + 2 < NCHUNK) {
            load_chunk(c + 2);
            asm volatile("cp.async.wait_group 2;" ::: "memory");
        } else if (c + 1 < NCHUNK) {
            asm volatile("cp.async.wait_group 1;" ::: "memory");
        } else {
            asm volatile("cp.async.wait_group 0;" ::: "memory");
        }
        __syncthreads();

        const u32 bufb  = sb + (u32)(c % 3) * BUFB;
        const u32 aBase = bufb + (u32)(a_row * 128);
        const u32 bBase = bufb + TILEB + (u32)(b_row * 128);

        #pragma unroll
        for (int ks = 0; ks < 4; ks++) {
            const u32 aOff = (u32)((ks * 32 + a_bh)) ^ a_mask;
            const u32 bOff = (u32)((ks * 32 + b_bh)) ^ b_mask;

            u32 b[8];
            #pragma unroll
            for (int nj = 0; nj < 2; nj++)
                ldmx4(&b[nj * 4], bBase + (u32)(nj * 16 * 128) + bOff);

            #pragma unroll
            for (int mi = 0; mi < 4; mi++) {
                u32 a[4];
                ldmx4(a, aBase + (u32)(mi * 16 * 128) + aOff);
                #pragma unroll
                for (int ni = 0; ni < 4; ni++)
                    mma_f16(acc[mi][ni], a, &b[(ni >> 1) * 4 + (ni & 1) * 2]);
            }
        }
        __syncthreads();
    }

    // ---- epilogue ----
    #pragma unroll
    for (int mi = 0; mi < 4; mi++) {
        int row = m0 + wm * 64 + mi * 16 + (lane >> 2);
        #pragma unroll
        for (int ni = 0; ni < 4; ni++) {
            int col = wn * 32 + ni * 8 + (lane & 3) * 2;
            *(float2*)(out + (size_t)row * COUT + col) =
                make_float2(acc[mi][ni][0], acc[mi][ni][1]);
            *(float2*)(out + (size_t)(row + 8) * COUT + col) =
                make_float2(acc[mi][ni][2], acc[mi][ni][3]);
        }
    }
}

// ================= launch =================
extern "C" void kernel_launch(void* const* d_in, const int* in_sizes, int n_in,
                              void* d_out, int out_size) {
    const float* query   = (const float*)d_in[0];
    const float* support = (const float*)d_in[1];
    const int*   nidx    = (const int*)d_in[2];
    const float* feats   = (const float*)d_in[3];
    const float* W       = (const float*)d_in[4];
    const float* kp      = (const float*)d_in[5];
    float* out = (float*)d_out;

    k1_agg<<<NTOT / Q1, NT1>>>(query, support, nidx, feats, kp, W);

    const int smem2 = 3 * BUFB;   // 98304
    cudaFuncSetAttribute(k2_gemm, cudaFuncAttributeMaxDynamicSharedMemorySize, smem2);
    k2_gemm<<<NTOT / 128, NT2, smem2>>>(out);
}

// round 10
// speedup vs baseline: 1.1757x; 1.0142x over previous
#include <cuda_runtime.h>
#include <cuda_fp16.h>
#include <cstdint>

#define NTOT 16384
#define KN   16
#define NP   15
#define CIN  64
#define COUT 128
#define KTOT (NP * CIN)        // 960

// ---------------- global scratch (allowed: __device__ arrays) ----------------
__device__ __half g_A[(size_t)NTOT * KTOT];     // [n][k] k-major, fp16
__device__ __half g_B[COUT * KTOT];             // [cout][k] k-major (= W^T), fp16

typedef unsigned long long u64;
typedef unsigned int u32;

__device__ __forceinline__ u32 h2pk(float a, float b) {
    __half ha = __float2half_rn(a), hb = __float2half_rn(b);
    unsigned short ua = *reinterpret_cast<unsigned short*>(&ha);
    unsigned short ub = *reinterpret_cast<unsigned short*>(&hb);
    return (u32)ua | ((u32)ub << 16);
}
__device__ __forceinline__ u32 smem_u32(const void* p) {
    u32 a; asm("{ .reg .u64 t; cvta.to.shared.u64 t, %1; cvt.u32.u64 %0, t; }"
               : "=r"(a) : "l"(p));
    return a;
}
__device__ __forceinline__ void ldmx4(u32* r, u32 addr) {
    asm volatile("ldmatrix.sync.aligned.m8n8.x4.shared.b16 {%0,%1,%2,%3}, [%4];"
                 : "=r"(r[0]), "=r"(r[1]), "=r"(r[2]), "=r"(r[3]) : "r"(addr));
}
__device__ __forceinline__ void ldmx4t(u32* r, u32 addr) {
    asm volatile("ldmatrix.sync.aligned.m8n8.x4.trans.shared.b16 {%0,%1,%2,%3}, [%4];"
                 : "=r"(r[0]), "=r"(r[1]), "=r"(r[2]), "=r"(r[3]) : "r"(addr));
}
__device__ __forceinline__ void mma_f16(float* d, const u32* a, const u32* b) {
    asm volatile("mma.sync.aligned.m16n8k16.row.col.f32.f16.f16.f32 "
                 "{%0,%1,%2,%3}, {%4,%5,%6,%7}, {%8,%9}, {%0,%1,%2,%3};"
                 : "+f"(d[0]), "+f"(d[1]), "+f"(d[2]), "+f"(d[3])
                 : "r"(a[0]), "r"(a[1]), "r"(a[2]), "r"(a[3]),
                   "r"(b[0]), "r"(b[1]));
}

// ====== kernel 1: gather + influence + tensor-core aggregation ======
// 32 queries/CTA, 256 threads, grid 512.
// smem: f-tile 512 rows x 128B (fp16, SW-swizzled) | infl 32 x [16p x 16k] fp16
#define Q1 32
#define NT1 256
#define OFF_F    0
#define OFF_INFL 65536
#define OFF_KP   81920
#define OFF_Q    82112
#define OFF_NIDX 82496
#define SMEM1    84544

__global__ __launch_bounds__(NT1)
void k1_agg(const float* __restrict__ query,
            const float* __restrict__ support,
            const int*   __restrict__ nidx,
            const float* __restrict__ feats,
            const float* __restrict__ kp,
            const float* __restrict__ W)
{
    extern __shared__ char sm[];
    const u32 sb = smem_u32(sm);
    __half* s_infl = (__half*)(sm + OFF_INFL);
    float*  s_kp   = (float*)(sm + OFF_KP);
    float*  s_q    = (float*)(sm + OFF_Q);
    int*    s_nidx = (int*)(sm + OFF_NIDX);

    const int tid = threadIdx.x;
    const int n0  = blockIdx.x * Q1;

    for (int i = tid; i < Q1 * KN; i += NT1) s_nidx[i] = nidx[n0 * KN + i];
    if (tid < NP * 3)   s_kp[tid] = kp[tid];
    if (tid < Q1 * 3)   s_q[tid]  = query[n0 * 3 + tid];
    __syncthreads();

    // ---- gather features -> fp16 swizzled smem tile ----
    // 512 rows x 256B fp32 = 8192 uint4 loads, coalesced; g = uint4 index
    #pragma unroll
    for (int i = 0; i < 32; i++) {
        int g   = tid + i * NT1;          // 0..8191
        int row = g >> 4;                 // (q,k) row
        int q16 = g & 15;                 // which 4-float group
        int m   = s_nidx[row];
        uint4 v = __ldg((const uint4*)(feats + (size_t)m * CIN) + q16);
        u32 lo = h2pk(__uint_as_float(v.x), __uint_as_float(v.y));
        u32 hi = h2pk(__uint_as_float(v.z), __uint_as_float(v.w));
        // byte offset in row: q16*8 ; 16B chunk = q16>>1, 8B half = q16&1
        u32 off = (u32)(row * 128) +
                  ((u32)((q16 >> 1) * 16) ^ ((u32)(row & 7) * 16)) +
                  (u32)((q16 & 1) * 8);
        *(uint2*)(sm + OFF_F + off) = make_uint2(lo, hi);
    }

    // ---- influences -> fp16 smem [q][p(16) x k(16)] (p=15 zero) ----
    #pragma unroll
    for (int pp = 0; pp < 2; pp++) {
        int pair = tid + pp * NT1;        // 0..511
        int qq = pair >> 4;
        int kk = pair & 15;
        int m  = s_nidx[pair];
        float rx = support[m * 3 + 0] - s_q[qq * 3 + 0];
        float ry = support[m * 3 + 1] - s_q[qq * 3 + 1];
        float rz = support[m * 3 + 2] - s_q[qq * 3 + 2];
        __half* ib = s_infl + qq * 256 + kk;   // row stride 16 halves
        #pragma unroll
        for (int p = 0; p < NP; p++) {
            float dx = rx - s_kp[p * 3 + 0];
            float dy = ry - s_kp[p * 3 + 1];
            float dz = rz - s_kp[p * 3 + 2];
            float d  = sqrtf(fmaf(dx, dx, fmaf(dy, dy, dz * dz)));
            ib[p * 16] = __float2half_rn(fmaxf(1.0f - d, 0.0f));
        }
        ib[15 * 16] = __half(0.0f);
    }
    __syncthreads();

    // ---- per-query mma aggregation: D[16p x 64c] = infl[16,16] @ f[16,64] ----
    const int wid  = tid >> 5;
    const int lane = tid & 31;

    // A-frag addressing (non-trans, rows = p, row stride 32B)
    const int aprow = (lane & 7) + ((lane >> 3) & 1) * 8;
    const u32 abh   = (u32)(((lane >> 4) & 1) * 16);
    // B-frag addressing (trans, rows = k in f-tile)
    const int mgrp  = lane >> 3;
    const int krow  = (mgrp & 1) * 8 + (lane & 7);
    const u32 cbyte0 = (u32)((mgrp >> 1) * 16);

    #pragma unroll
    for (int i = 0; i < 4; i++) {
        const int q = wid * 4 + i;

        u32 a[4];
        ldmx4(a, sb + OFF_INFL + (u32)(q * 512 + aprow * 32) + abh);

        float acc[8][4];
        #pragma unroll
        for (int g = 0; g < 8; g++)
            #pragma unroll
            for (int e = 0; e < 4; e++) acc[g][e] = 0.0f;

        const int frow = q * 16 + krow;
        const u32 fbase = sb + OFF_F + (u32)(frow * 128);
        const u32 swz   = (u32)((krow & 7) * 16);
        #pragma unroll
        for (int cc = 0; cc < 4; cc++) {
            u32 b[4];
            ldmx4t(b, fbase + (((u32)(cc * 32) + cbyte0) ^ swz));
            mma_f16(acc[2 * cc],     a, &b[0]);
            mma_f16(acc[2 * cc + 1], a, &b[2]);
        }

        // stage D -> fp16 into the (now dead) f-tile of query q, swizzled
        const int prow = lane >> 2;
        const int c4   = lane & 3;
        #pragma unroll
        for (int g = 0; g < 8; g++) {
            u32 lo = h2pk(acc[g][0], acc[g][1]);   // row prow
            u32 hi = h2pk(acc[g][2], acc[g][3]);   // row prow+8
            u32 base = sb + OFF_F + (u32)(q * 16 * 128);
            u32 x = (u32)(g * 16) ;
            *(u32*)(sm + OFF_F + (q * 16 + prow) * 128 +
                    ((x ^ ((u32)(prow & 7) * 16)) + (u32)(c4 * 4))) = lo;
            *(u32*)(sm + OFF_F + (q * 16 + prow + 8) * 128 +
                    ((x ^ ((u32)((prow + 8) & 7) * 16)) + (u32)(c4 * 4))) = hi;
            (void)base;
        }
        __syncwarp();

        // coalesced write-out: 15 p-rows x 128B -> g_A[n0+q][p*64 + ...]
        #pragma unroll
        for (int rnd = 0; rnd < 4; rnd++) {
            int u = lane + rnd * 32;
            if (u < 120) {
                int p = u >> 3, j = u & 7;
                uint4 v = *(uint4*)(sm + OFF_F + (q * 16 + p) * 128 +
                                    (((u32)(j * 16)) ^ ((u32)(p & 7) * 16)));
                *(uint4*)(g_A + (size_t)(n0 + q) * KTOT + p * CIN + j * 8) = v;
            }
        }
        __syncwarp();
    }

    // ---- fused W conversion: blocks 0..119 convert W -> B fp16 ----
    if (blockIdx.x < 120) {
        int idx4 = blockIdx.x * NT1 + tid;     // 0..30719, 4 k-elems each
        int n  = idx4 / 240;
        int kq = idx4 - n * 240;
        int k  = kq * 4;
        int p  = k >> 6, cin = k & 63;
        const float* wp = W + p * CIN * COUT + cin * COUT + n;
        float w0 = __ldg(wp);
        float w1 = __ldg(wp + COUT);
        float w2 = __ldg(wp + 2 * COUT);
        float w3 = __ldg(wp + 3 * COUT);
        uint2 vh = make_uint2(h2pk(w0, w1), h2pk(w2, w3));
        *(uint2*)(g_B + (size_t)n * KTOT + k) = vh;
    }
}

// ================= kernel 2: mma.sync fp16 GEMM (R7 2-stage, verified) =======
#define NT2 256
#define NCHUNK 15
#define TILEB 16384
#define BUFB  (2 * TILEB)

__global__ __launch_bounds__(NT2, 1)
void k2_gemm(float* __restrict__ out)
{
    extern __shared__ char smem[];
    const u32 sb = smem_u32(smem);
    const int tid  = threadIdx.x;
    const int wid  = tid >> 5;
    const int lane = tid & 31;
    const int wm   = wid >> 2;
    const int wn   = wid & 3;
    const int m0   = blockIdx.x * 128;

    const int a_row  = wm * 64 + (lane & 7) + ((lane >> 3) & 1) * 8;
    const int a_bh   = ((lane >> 4) & 1) * 16;
    const u32 a_mask = (u32)((a_row & 7) * 16);
    const int b_row  = wn * 32 + (lane & 7) + ((lane >> 4) & 1) * 8;
    const int b_bh   = ((lane >> 3) & 1) * 16;
    const u32 b_mask = (u32)((b_row & 7) * 16);

    float acc[4][4][4];
    #pragma unroll
    for (int mi = 0; mi < 4; mi++)
        #pragma unroll
        for (int ni = 0; ni < 4; ni++)
            #pragma unroll
            for (int e = 0; e < 4; e++) acc[mi][ni][e] = 0.0f;

    auto load_chunk = [&](int c) {
        u32 dstb = sb + (u32)(c & 1) * BUFB;
        #pragma unroll
        for (int j = 0; j < 8; j++) {
            int idx = tid + j * NT2;
            int t    = idx >> 10;
            int win  = idx & 1023;
            int row  = win >> 3;
            int c16  = win & 7;
            const __half* src = (t == 0 ? g_A + (size_t)(m0 + row) * KTOT
                                        : g_B + (size_t)row * KTOT)
                                + c * 64 + c16 * 8;
            u32 dst = dstb + (u32)t * TILEB
                    + (u32)(row * 128 + ((c16 * 16) ^ ((row & 7) * 16)));
            asm volatile("cp.async.cg.shared.global [%0], [%1], 16;"
                         :: "r"(dst), "l"(src) : "memory");
        }
        asm volatile("cp.async.commit_group;" ::: "memory");
    };

    load_chunk(0);

    for (int c = 0; c < NCHUNK; c++) {
        if (c + 1 < NCHUNK) {
            load_chunk(c + 1);
            asm volatile("cp.async.wait_group 1;" ::: "memory");
        } else {
            asm volatile("cp.async.wait_group 0;" ::: "memory");
        }
        __syncthreads();

        const u32 bufb  = sb + (u32)(c & 1) * BUFB;
        const u32 aBase = bufb + (u32)(a_row * 128);
        const u32 bBase = bufb + TILEB + (u32)(b_row * 128);

        #pragma unroll
        for (int ks = 0; ks < 4; ks++) {
            const u32 aOff = (u32)((ks * 32 + a_bh)) ^ a_mask;
            const u32 bOff = (u32)((ks * 32 + b_bh)) ^ b_mask;

            u32 b[8];
            #pragma unroll
            for (int nj = 0; nj < 2; nj++)
                ldmx4(&b[nj * 4], bBase + (u32)(nj * 16 * 128) + bOff);

            #pragma unroll
            for (int mi = 0; mi < 4; mi++) {
                u32 a[4];
                ldmx4(a, aBase + (u32)(mi * 16 * 128) + aOff);
                #pragma unroll
                for (int ni = 0; ni < 4; ni++)
                    mma_f16(acc[mi][ni], a, &b[(ni >> 1) * 4 + (ni & 1) * 2]);
            }
        }
        __syncthreads();
    }

    #pragma unroll
    for (int mi = 0; mi < 4; mi++) {
        int row = m0 + wm * 64 + mi * 16 + (lane >> 2);
        #pragma unroll
        for (int ni = 0; ni < 4; ni++) {
            int col = wn * 32 + ni * 8 + (lane & 3) * 2;
            *(float2*)(out + (size_t)row * COUT + col) =
                make_float2(acc[mi][ni][0], acc[mi][ni][1]);
            *(float2*)(out + (size_t)(row + 8) * COUT + col) =
                make_float2(acc[mi][ni][2], acc[mi][ni][3]);
        }
    }
}

// ================= launch =================
extern "C" void kernel_launch(void* const* d_in, const int* in_sizes, int n_in,
                              void* d_out, int out_size) {
    const float* query   = (const float*)d_in[0];
    const float* support = (const float*)d_in[1];
    const int*   nidx    = (const int*)d_in[2];
    const float* feats   = (const float*)d_in[3];
    const float* W       = (const float*)d_in[4];
    const float* kp      = (const float*)d_in[5];
    float* out = (float*)d_out;

    cudaFuncSetAttribute(k1_agg, cudaFuncAttributeMaxDynamicSharedMemorySize, SMEM1);
    k1_agg<<<NTOT / Q1, NT1, SMEM1>>>(query, support, nidx, feats, kp, W);

    const int smem2 = 2 * BUFB;   // 65536
    cudaFuncSetAttribute(k2_gemm, cudaFuncAttributeMaxDynamicSharedMemorySize, smem2);
    k2_gemm<<<NTOT / 128, NT2, smem2>>>(out);
}